// round 7
// baseline (speedup 1.0000x reference)
#include <cuda_runtime.h>
#include <cuda_bf16.h>
#include <math_constants.h>

// Tiered grid NN lookup + sigmoid(saliency). 16^3 grid over [0,100]^3
// (cell 6.25). Pipeline: memset(counters) -> prep (bin radar + queries into
// fixed-capacity buckets) -> query (one warp per cell).
// Tier-1: 3x3x3 neighborhood (~33 pts) staged to smem; excluded points have
//   true dist^2 > 39.0625, so best < 38.0 (>=1.0 rounding slack) is final.
// Tier-2: 5x5x5 from global buckets; excluded > 156.25, best < 155.25 final.
// Tier-3: full brute-force scan. Bucket overflow anywhere -> full scan.
// All reductions are u64 min over (ordered-dist | orig idx): order-invariant,
// ties resolve to the smallest original index == jnp.argmin first-occurrence.
// Distance arithmetic bit-identical to the reference:
//   l2/r2 : round(x*x)+round(y*y)+round(z*z), rounded adds (NO fma)
//   cross : fma chain (K=3 GEMM style);  dist : fmaf(-2,c, round(l2+r2))

#define GDIM   16
#define NCELL  (GDIM * GDIM * GDIM)
#define CELLW  6.25f
#define MAXNPT 8192
#define MAXV   65536
#define CAP_R  16
#define CAP_Q  64
#define SCAP   192
#define PB     256

#define T1_KEY 0xC2180000u   /* ordered(38.0f)   */
#define T2_KEY 0xC31B4000u   /* ordered(155.25f) */

__device__ int    g_counts[2 * NCELL];        // [0,NCELL): radar, rest: query
__device__ float4 g_pts[MAXNPT];              // raw order {x,y,z,r2}
__device__ float  g_sal[MAXNPT];
__device__ float4 g_rbucket[NCELL * CAP_R];
__device__ int    g_rbidx[NCELL * CAP_R];
__device__ int    g_qbucket[NCELL * CAP_Q];
__device__ int    g_qcell[MAXV];

__device__ __forceinline__ float sum_sq_ref(float x, float y, float z) {
    float x2 = __fmul_rn(x, x);
    float y2 = __fmul_rn(y, y);
    float z2 = __fmul_rn(z, z);
    return __fadd_rn(__fadd_rn(x2, y2), z2);
}

__device__ __forceinline__ int cell_coord(float x) {
    int c = (int)(x * (1.0f / CELLW));
    return min(max(c, 0), GDIM - 1);
}

__device__ __forceinline__ unsigned float_ordered(float f) {
    unsigned u = __float_as_uint(f);
    return u ^ (((unsigned)((int)u >> 31)) | 0x80000000u);
}

__device__ __forceinline__ unsigned long long dist_key(
    float x, float y, float z, float l2, float4 pt, int idx) {
    float c = fmaf(z, pt.z, fmaf(y, pt.y, __fmul_rn(x, pt.x)));
    float d = fmaf(-2.0f, c, __fadd_rn(l2, pt.w));
    return ((unsigned long long)float_ordered(d) << 32) | (unsigned)idx;
}

__global__ void prep_kernel(const float* __restrict__ feat,
                            const float* __restrict__ rcoords,
                            const float* __restrict__ lcoords,
                            int N, int V) {
    int t = blockIdx.x * blockDim.x + threadIdx.x;
    if (t < N) {
        int n = t;
        float rx = rcoords[3 * n + 0];
        float ry = rcoords[3 * n + 1];
        float rz = rcoords[3 * n + 2];
        float4 p = make_float4(rx, ry, rz, sum_sq_ref(rx, ry, rz));
        g_pts[n] = p;
        float f0 = feat[64 * n + 0];
        float f1 = feat[64 * n + 1];
        float s = __fadd_rn(__fmul_rn(0.6f, fabsf(f0)), __fmul_rn(0.4f, f1));
        g_sal[n] = 1.0f / (1.0f + expf(-s));
        int c = (cell_coord(rz) * GDIM + cell_coord(ry)) * GDIM + cell_coord(rx);
        int pos = atomicAdd(&g_counts[c], 1);
        if (pos < CAP_R) {
            g_rbucket[c * CAP_R + pos] = p;
            g_rbidx[c * CAP_R + pos] = n;
        }
    } else if (t < N + V) {
        int v = t - N;
        float x = lcoords[3 * v + 0];
        float y = lcoords[3 * v + 1];
        float z = lcoords[3 * v + 2];
        int c = (cell_coord(z) * GDIM + cell_coord(y)) * GDIM + cell_coord(x);
        g_qcell[v] = c;
        int pos = atomicAdd(&g_counts[NCELL + c], 1);
        if (pos < CAP_Q) g_qbucket[c * CAP_Q + pos] = v;
    }
}

// Tier-2: scan 5x5x5 from global buckets. Returns updated key; sets *ovf if
// any visited bucket overflowed (-> caller must full-scan).
__device__ unsigned long long tier2_scan(
    float x, float y, float z, float l2,
    int cx, int cy, int cz, unsigned long long best, bool* ovf) {
    int x0 = max(cx - 2, 0), x1 = min(cx + 2, GDIM - 1);
    int y0 = max(cy - 2, 0), y1 = min(cy + 2, GDIM - 1);
    int z0 = max(cz - 2, 0), z1 = min(cz + 2, GDIM - 1);
    for (int dz = z0; dz <= z1; dz++)
        for (int dy = y0; dy <= y1; dy++)
            for (int dx = x0; dx <= x1; dx++) {
                int c = (dz * GDIM + dy) * GDIM + dx;
                int cnt = g_counts[c];
                if (cnt > CAP_R) { *ovf = true; cnt = CAP_R; }
                for (int i = 0; i < cnt; i++)
                    best = min(best, dist_key(x, y, z, l2,
                                              g_rbucket[c * CAP_R + i],
                                              g_rbidx[c * CAP_R + i]));
            }
    return best;
}

__device__ unsigned long long full_scan(
    float x, float y, float z, float l2, unsigned long long best, int N) {
    for (int p = 0; p < N; p++)
        best = min(best, dist_key(x, y, z, l2, g_pts[p], p));
    return best;
}

__global__ void __launch_bounds__(32) query_kernel(
    const float* __restrict__ lcoords, float* __restrict__ out,
    int N, int V) {
    __shared__ float4 s_pts[SCAP];
    __shared__ int    s_idx[SCAP];

    const int cell = blockIdx.x;
    const int qcnt = g_counts[NCELL + cell];
    if (qcnt == 0) return;

    const int cz = cell >> 8, cy = (cell >> 4) & 15, cx = cell & 15;
    const int x0 = max(cx - 1, 0), x1 = min(cx + 1, GDIM - 1);
    const int y0 = max(cy - 1, 0), y1 = min(cy + 1, GDIM - 1);
    const int z0 = max(cz - 1, 0), z1 = min(cz + 1, GDIM - 1);
    const int nx = x1 - x0 + 1, ny = y1 - y0 + 1, nz = z1 - z0 + 1;
    const int ncells = nx * ny * nz;          // <= 27
    const int lane = threadIdx.x;
    const unsigned FULL = 0xffffffffu;

    // Stage tier-1 neighborhood: one cell per lane, shfl prefix for offsets.
    int mycell = -1, cnt = 0;
    if (lane < ncells) {
        int lx = lane % nx, ly = (lane / nx) % ny, lz = lane / (nx * ny);
        mycell = ((z0 + lz) * GDIM + (y0 + ly)) * GDIM + (x0 + lx);
        cnt = g_counts[mycell];
    }
    const bool r_ovf = __any_sync(FULL, cnt > CAP_R);
    cnt = min(cnt, CAP_R);
    int off = cnt;
    #pragma unroll
    for (int s = 1; s < 32; s <<= 1) {
        int u = __shfl_up_sync(FULL, off, s);
        if (lane >= s) off += u;
    }
    const int total = __shfl_sync(FULL, off, 31);
    off -= cnt;                               // exclusive prefix
    const bool use_smem = !r_ovf && (total <= SCAP - 3);
    if (use_smem && lane < ncells) {
        for (int i = 0; i < cnt; i++) {
            s_pts[off + i] = g_rbucket[mycell * CAP_R + i];
            s_idx[off + i] = g_rbidx[mycell * CAP_R + i];
        }
    }
    const int padded = (total + 3) & ~3;
    if (use_smem && lane < padded - total) {
        s_pts[total + lane] = make_float4(0.f, 0.f, 0.f, CUDART_INF_F);
        s_idx[total + lane] = 0;
    }
    __syncwarp();

    const bool q_ovf = (qcnt > CAP_Q);
    const int qn = q_ovf ? V : qcnt;
    for (int q = lane; q < qn; q += 32) {
        int v;
        if (q_ovf) { v = q; if (g_qcell[v] != cell) continue; }
        else       { v = g_qbucket[cell * CAP_Q + q]; }

        const float x = lcoords[3 * v + 0];
        const float y = lcoords[3 * v + 1];
        const float z = lcoords[3 * v + 2];
        const float l2 = sum_sq_ref(x, y, z);

        unsigned long long best = ~0ull;
        if (use_smem) {
            unsigned long long b0 = ~0ull, b1 = ~0ull, b2 = ~0ull, b3 = ~0ull;
            for (int j = 0; j < padded; j += 4) {
                b0 = min(b0, dist_key(x, y, z, l2, s_pts[j + 0], s_idx[j + 0]));
                b1 = min(b1, dist_key(x, y, z, l2, s_pts[j + 1], s_idx[j + 1]));
                b2 = min(b2, dist_key(x, y, z, l2, s_pts[j + 2], s_idx[j + 2]));
                b3 = min(b3, dist_key(x, y, z, l2, s_pts[j + 3], s_idx[j + 3]));
            }
            best = min(min(b0, b1), min(b2, b3));
        }

        if (r_ovf) {
            best = full_scan(x, y, z, l2, best, N);
        } else {
            if ((unsigned)(best >> 32) >= T1_KEY) {
                bool t2_ovf = false;
                best = tier2_scan(x, y, z, l2, cx, cy, cz, best, &t2_ovf);
                if (t2_ovf || (unsigned)(best >> 32) >= T2_KEY)
                    best = full_scan(x, y, z, l2, best, N);
            }
        }
        out[v] = g_sal[(unsigned)best];
    }
}

extern "C" void kernel_launch(void* const* d_in, const int* in_sizes, int n_in,
                              void* d_out, int out_size) {
    const float* feat    = (const float*)d_in[0];   // [N, 64]
    const float* lcoords = (const float*)d_in[1];   // [V, 3]
    const float* rcoords = (const float*)d_in[2];   // [N, 3]
    float* out = (float*)d_out;                     // [V]

    int N = in_sizes[0] / 64;
    int V = in_sizes[1] / 3;
    int NV = N + V;

    void* counts_ptr = nullptr;
    cudaGetSymbolAddress(&counts_ptr, g_counts);
    cudaMemsetAsync(counts_ptr, 0, 2 * NCELL * sizeof(int), 0);

    prep_kernel<<<(NV + PB - 1) / PB, PB>>>(feat, rcoords, lcoords, N, V);
    query_kernel<<<NCELL, 32>>>(lcoords, out, N, V);
}

// round 8
// speedup vs baseline: 1.7290x; 1.7290x over previous
#include <cuda_runtime.h>
#include <cuda_bf16.h>
#include <math_constants.h>

// Grid NN lookup + sigmoid(saliency), fixed-capacity cell buckets (8^3 grid,
// cell 12.5 over [0,100]^3). memset(counters) -> prep (bin radar+queries via
// atomicAdd) -> query (block per cell, 256 thr: stage 3x3x3 neighborhood to
// smem once, 2 threads per query scan it in lockstep, shfl-merged).
// Bucket order nondeterministic but reductions are u64 min over
// (ordered-dist | orig idx): order-invariant, ties -> smallest original index
// == jnp.argmin first occurrence. Overflow anywhere -> full scan fallback.
// Excluded points (outside 3x3x3) have true dist^2 > 156.25; best < 155.25
// (>=1.0 rounding slack) is provably final, else full brute-force.
// Distance arithmetic bit-identical to the reference:
//   l2/r2 : round(x*x)+round(y*y)+round(z*z), rounded adds (NO fma)
//   cross : fma chain (K=3 GEMM style);  dist : fmaf(-2,c, round(l2+r2))

#define GDIM   8
#define NCELL  (GDIM * GDIM * GDIM)
#define CELLW  12.5f
#define MAXNPT 8192
#define MAXV   65536
#define CAP_R  64
#define CAP_Q  192
#define SCAP   1024
#define PB     256
#define QBLK   256

#define FINAL_KEY 0xC31B4000u   /* ordered(155.25f) */

__device__ int    g_counts[2 * NCELL];        // [0,512): radar, [512,1024): query
__device__ float4 g_pts[MAXNPT];              // raw order {x,y,z,r2} (fallback)
__device__ float  g_sal[MAXNPT];
__device__ float4 g_rbucket[NCELL * CAP_R];
__device__ int    g_rbidx[NCELL * CAP_R];
__device__ int    g_qbucket[NCELL * CAP_Q];
__device__ int    g_qcell[MAXV];

__device__ __forceinline__ float sum_sq_ref(float x, float y, float z) {
    float x2 = __fmul_rn(x, x);
    float y2 = __fmul_rn(y, y);
    float z2 = __fmul_rn(z, z);
    return __fadd_rn(__fadd_rn(x2, y2), z2);
}

__device__ __forceinline__ int cell_coord(float x) {
    int c = (int)(x * (1.0f / CELLW));
    return min(max(c, 0), GDIM - 1);
}

__device__ __forceinline__ unsigned float_ordered(float f) {
    unsigned u = __float_as_uint(f);
    return (u & 0x80000000u) ? ~u : (u | 0x80000000u);
}

__device__ __forceinline__ unsigned long long dist_key(
    float x, float y, float z, float l2, float4 pt, int idx) {
    float c = fmaf(z, pt.z, fmaf(y, pt.y, __fmul_rn(x, pt.x)));
    float d = fmaf(-2.0f, c, __fadd_rn(l2, pt.w));
    return ((unsigned long long)float_ordered(d) << 32) | (unsigned)idx;
}

__global__ void prep_kernel(const float* __restrict__ feat,
                            const float* __restrict__ rcoords,
                            const float* __restrict__ lcoords,
                            int N, int V) {
    int t = blockIdx.x * blockDim.x + threadIdx.x;
    if (t < N) {
        int n = t;
        float rx = rcoords[3 * n + 0];
        float ry = rcoords[3 * n + 1];
        float rz = rcoords[3 * n + 2];
        float4 p = make_float4(rx, ry, rz, sum_sq_ref(rx, ry, rz));
        g_pts[n] = p;
        float f0 = feat[64 * n + 0];
        float f1 = feat[64 * n + 1];
        float s = __fadd_rn(__fmul_rn(0.6f, fabsf(f0)), __fmul_rn(0.4f, f1));
        g_sal[n] = 1.0f / (1.0f + expf(-s));
        int c = (cell_coord(rz) * GDIM + cell_coord(ry)) * GDIM + cell_coord(rx);
        int pos = atomicAdd(&g_counts[c], 1);
        if (pos < CAP_R) {
            g_rbucket[c * CAP_R + pos] = p;
            g_rbidx[c * CAP_R + pos] = n;
        }
    } else if (t < N + V) {
        int v = t - N;
        float x = lcoords[3 * v + 0];
        float y = lcoords[3 * v + 1];
        float z = lcoords[3 * v + 2];
        int c = (cell_coord(z) * GDIM + cell_coord(y)) * GDIM + cell_coord(x);
        g_qcell[v] = c;
        int pos = atomicAdd(&g_counts[NCELL + c], 1);
        if (pos < CAP_Q) g_qbucket[c * CAP_Q + pos] = v;
    }
}

__global__ void __launch_bounds__(QBLK) query_kernel(
    const float* __restrict__ lcoords, float* __restrict__ out,
    int N, int V) {
    __shared__ float4 s_pts[SCAP];
    __shared__ int    s_idx[SCAP];

    const int cell = blockIdx.x;
    const int qcnt = g_counts[NCELL + cell];
    if (qcnt == 0) return;

    const int cz = cell >> 6, cy = (cell >> 3) & 7, cx = cell & 7;
    const int x0 = max(cx - 1, 0), x1 = min(cx + 1, GDIM - 1);
    const int y0 = max(cy - 1, 0), y1 = min(cy + 1, GDIM - 1);
    const int z0 = max(cz - 1, 0), z1 = min(cz + 1, GDIM - 1);
    const int tid  = threadIdx.x;
    const int wid  = tid >> 5;
    const int lane = tid & 31;

    // Stage the 3x3x3 neighborhood buckets into smem. Cells round-robin over
    // the 8 warps; counts are broadcast loads so every thread tracks dst.
    bool ovf = false;
    int  dst = 0, ci = 0;
    for (int dz = z0; dz <= z1; dz++)
        for (int dy = y0; dy <= y1; dy++)
            for (int dx = x0; dx <= x1; dx++) {
                int c = (dz * GDIM + dy) * GDIM + dx;
                int cnt = g_counts[c];
                ovf |= (cnt > CAP_R);
                cnt = min(cnt, CAP_R);
                if (((ci++) & 7) == wid && dst + cnt <= SCAP) {
                    for (int i = lane; i < cnt; i += 32) {
                        s_pts[dst + i] = g_rbucket[c * CAP_R + i];
                        s_idx[dst + i] = g_rbidx[c * CAP_R + i];
                    }
                }
                dst += cnt;
            }
    const int  total    = dst;
    const bool use_smem = !ovf && (total <= SCAP - 8);
    const int  padded   = (total + 7) & ~7;      // multiple of 8 for 2-halves x4
    if (use_smem && tid < padded - total) {
        s_pts[total + tid] = make_float4(0.f, 0.f, 0.f, CUDART_INF_F);
        s_idx[total + tid] = 0;
    }
    __syncthreads();

    // 2 threads per query: lane pairs (2k, 2k+1) share query q; halves take
    // alternating groups of 4 candidates, merged via shfl_xor(1).
    const int  half  = tid & 1;
    const bool q_ovf = (qcnt > CAP_Q);
    const int  qn    = q_ovf ? V : qcnt;
    for (int q = (tid >> 1); q < qn; q += (QBLK >> 1)) {
        int v;
        if (q_ovf) { v = q; if (g_qcell[v] != cell) continue; }
        else       { v = g_qbucket[cell * CAP_Q + q]; }

        const float x = lcoords[3 * v + 0];
        const float y = lcoords[3 * v + 1];
        const float z = lcoords[3 * v + 2];
        const float l2 = sum_sq_ref(x, y, z);

        unsigned long long best = ~0ull;
        if (use_smem) {
            unsigned long long b0 = ~0ull, b1 = ~0ull, b2 = ~0ull, b3 = ~0ull;
            for (int j = half * 4; j < padded; j += 8) {
                b0 = min(b0, dist_key(x, y, z, l2, s_pts[j + 0], s_idx[j + 0]));
                b1 = min(b1, dist_key(x, y, z, l2, s_pts[j + 1], s_idx[j + 1]));
                b2 = min(b2, dist_key(x, y, z, l2, s_pts[j + 2], s_idx[j + 2]));
                b3 = min(b3, dist_key(x, y, z, l2, s_pts[j + 3], s_idx[j + 3]));
            }
            best = min(min(b0, b1), min(b2, b3));
        }
        best = min(best, __shfl_xor_sync(0xffffffffu, best, 1));

        // Finality: excluded true dist^2 > 156.25, slack >= 1.0 for rounding.
        if ((unsigned)(best >> 32) >= FINAL_KEY) {
            for (int p = half; p < N; p += 2)
                best = min(best, dist_key(x, y, z, l2, g_pts[p], p));
            best = min(best, __shfl_xor_sync(0xffffffffu, best, 1));
        }

        if (half == 0)
            out[v] = g_sal[(unsigned)best];
    }
}

extern "C" void kernel_launch(void* const* d_in, const int* in_sizes, int n_in,
                              void* d_out, int out_size) {
    const float* feat    = (const float*)d_in[0];   // [N, 64]
    const float* lcoords = (const float*)d_in[1];   // [V, 3]
    const float* rcoords = (const float*)d_in[2];   // [N, 3]
    float* out = (float*)d_out;                     // [V]

    int N = in_sizes[0] / 64;
    int V = in_sizes[1] / 3;
    int NV = N + V;

    void* counts_ptr = nullptr;
    cudaGetSymbolAddress(&counts_ptr, g_counts);
    cudaMemsetAsync(counts_ptr, 0, 2 * NCELL * sizeof(int), 0);

    prep_kernel<<<(NV + PB - 1) / PB, PB>>>(feat, rcoords, lcoords, N, V);
    query_kernel<<<NCELL, QBLK>>>(lcoords, out, N, V);
}